// round 10
// baseline (speedup 1.0000x reference)
#include <cuda_runtime.h>
#include <cuda_fp16.h>
#include <cstdint>

// Fixed shapes
#define TLEN 2048
#define HD   64
#define BPB  4
#define NTHREADS 512
#define NBLOCKS  128

// SMEM layout in u32 units:
//  ping-pong fp16 h buffers: each = hi[8 rows x 68 u32] + lo[8 x 68]
//  (row = batch, 136 halves per row = K-concat [h1(64) | h2(64)] + pad)
#define HB0  0
#define HB1  1088
#define GB   2176         // gbuf f32 [512][10]
#define H2F  7296         // h2 fp32 [4*64]
#define MS   7552         // fc1 activations [512]
#define SMEM_U32 8064

__device__ __forceinline__ float tanh_ap(float v) {
    float r;
    asm("tanh.approx.f32 %0, %1;" : "=f"(r) : "f"(v));
    return r;
}
__device__ __forceinline__ float sigm_ap(float v) {
    return fmaf(0.5f, tanh_ap(0.5f * v), 0.5f);
}
__device__ __forceinline__ uint32_t packh(float x, float y) {
    __half2 h = __floats2half2_rn(x, y);
    return *reinterpret_cast<uint32_t*>(&h);
}
__device__ __forceinline__ float lof(float x) {
    return x - __half2float(__float2half_rn(x));
}
__device__ __forceinline__ void mma16816(float* c, const uint32_t* a,
                                         uint32_t b0, uint32_t b1) {
    asm volatile(
        "mma.sync.aligned.m16n8k16.row.col.f32.f16.f16.f32 "
        "{%0,%1,%2,%3}, {%4,%5,%6,%7}, {%8,%9}, {%0,%1,%2,%3};"
        : "+f"(c[0]), "+f"(c[1]), "+f"(c[2]), "+f"(c[3])
        : "r"(a[0]), "r"(a[1]), "r"(a[2]), "r"(a[3]), "r"(b0), "r"(b1));
}

__global__ __launch_bounds__(NTHREADS, 1)
void lstm2_mma_kernel(
    const float* __restrict__ x,      // [B, T]
    const float* __restrict__ w_ih0,  // [256, 1]
    const float* __restrict__ w_hh0,  // [256, 64]
    const float* __restrict__ b_ih0,  // [256]
    const float* __restrict__ b_hh0,  // [256]
    const float* __restrict__ w_ih1,  // [256, 64]
    const float* __restrict__ w_hh1,  // [256, 64]
    const float* __restrict__ b_ih1,  // [256]
    const float* __restrict__ b_hh1,  // [256]
    const float* __restrict__ fc1_w,  // [128, 64]
    const float* __restrict__ fc1_b,  // [128]
    const float* __restrict__ fc2_w,  // [10, 128]
    const float* __restrict__ fc2_b,  // [10]
    float* __restrict__ out)          // [B, 10]
{
    __shared__ uint32_t smu[SMEM_U32];
    float* gbuf = (float*)(smu + GB);     // [512 gate rows][10] (cols 0-3 = batch)
    float* h2f  = (float*)(smu + H2F);
    float* ms   = (float*)(smu + MS);

    const int tid = threadIdx.x;
    const int l   = tid & 31;
    const int w   = tid >> 5;         // warp 0..15
    const int lq  = l >> 2;           // A row group / B col (batch) 0..7
    const int lr  = l & 3;            // k-pair group
    const int r0  = 16 * w + lq;      // this warp's gate rows
    const int r1  = r0 + 8;
    const int bbase = blockIdx.x * BPB;

    // ---- Pack weights into register-resident A fragments (hi + lo fp16) ----
    uint32_t aL1h[4][4], aL1l[4][4], aL2h[8][4], aL2l[8][4];
    #pragma unroll
    for (int kt = 0; kt < 4; ++kt) {
        const int k = 16 * kt + 2 * lr;
        const float w00 = w_hh0[r0 * HD + k],     w01 = w_hh0[r0 * HD + k + 1];
        const float w10 = w_hh0[r1 * HD + k],     w11 = w_hh0[r1 * HD + k + 1];
        const float w02 = w_hh0[r0 * HD + k + 8], w03 = w_hh0[r0 * HD + k + 9];
        const float w12 = w_hh0[r1 * HD + k + 8], w13 = w_hh0[r1 * HD + k + 9];
        aL1h[kt][0] = packh(w00, w01); aL1h[kt][1] = packh(w10, w11);
        aL1h[kt][2] = packh(w02, w03); aL1h[kt][3] = packh(w12, w13);
        aL1l[kt][0] = packh(lof(w00), lof(w01)); aL1l[kt][1] = packh(lof(w10), lof(w11));
        aL1l[kt][2] = packh(lof(w02), lof(w03)); aL1l[kt][3] = packh(lof(w12), lof(w13));
    }
    #pragma unroll
    for (int kt = 0; kt < 8; ++kt) {
        const int k = 16 * kt + 2 * lr;
        const float* s0 = (k < 64) ? (w_ih1 + r0 * HD + k) : (w_hh1 + r0 * HD + k - 64);
        const float* s1 = (k < 64) ? (w_ih1 + r1 * HD + k) : (w_hh1 + r1 * HD + k - 64);
        const float w00 = s0[0], w01 = s0[1], w02 = s0[8], w03 = s0[9];
        const float w10 = s1[0], w11 = s1[1], w12 = s1[8], w13 = s1[9];
        aL2h[kt][0] = packh(w00, w01); aL2h[kt][1] = packh(w10, w11);
        aL2h[kt][2] = packh(w02, w03); aL2h[kt][3] = packh(w12, w13);
        aL2l[kt][0] = packh(lof(w00), lof(w01)); aL2l[kt][1] = packh(lof(w10), lof(w11));
        aL2l[kt][2] = packh(lof(w02), lof(w03)); aL2l[kt][3] = packh(lof(w12), lof(w13));
    }

    // ---- Pointwise ownership ----
    const int grp = tid >> 8;             // 0: layer1, 1: layer2
    const int pb  = (tid >> 6) & 3;       // batch
    const int pu  = tid & 63;             // hidden unit
    float bb[4], wx[4];
    #pragma unroll
    for (int gt = 0; gt < 4; ++gt) {
        const int jg = gt * 64 + pu;
        bb[gt] = grp ? (b_ih1[jg] + b_hh1[jg]) : (b_ih0[jg] + b_hh0[jg]);
        wx[gt] = grp ? 0.0f : w_ih0[jg];
    }
    float cst = 0.0f;

    for (int i = tid; i < SMEM_U32; i += NTHREADS) smu[i] = 0u;
    __syncthreads();

    const float* xrow = x + (bbase + pb) * TLEN;
    float xcur = grp ? 0.0f : xrow[0];

    // Pipelined: iter t computes L1 gates(t) [h1(t-1), x(t)] and L2 gates(t-1)
    // [h1(t-1), h2(t-2)]. hb read = buf(t&1), write = other.
    for (int t = 0; t <= TLEN; ++t) {
        const uint32_t* rd_hi = smu + ((t & 1) ? HB1 : HB0);
        const uint32_t* rd_lo = rd_hi + 544;
        const int bidx = lq * 68 + lr;    // banks (4*lq + lr) -> conflict-free

        float C1a[4] = {0,0,0,0}, C1b[4] = {0,0,0,0};
        float C2a[4] = {0,0,0,0}, C2b[4] = {0,0,0,0};

        #pragma unroll
        for (int kt = 0; kt < 8; ++kt) {
            const uint32_t bh0 = rd_hi[bidx + kt * 8];
            const uint32_t bh1 = rd_hi[bidx + kt * 8 + 4];
            const uint32_t bl0 = rd_lo[bidx + kt * 8];
            const uint32_t bl1 = rd_lo[bidx + kt * 8 + 4];
            if (kt < 4) {
                mma16816(C1a, aL1h[kt], bh0, bh1);      // Whi*Bhi
                mma16816(C2a, aL2h[kt], bh0, bh1);
                mma16816(C1b, aL1l[kt], bh0, bh1);      // Wlo*Bhi
                mma16816(C2b, aL2l[kt], bh0, bh1);
                mma16816(C1a, aL1h[kt], bl0, bl1);      // Whi*Blo
                mma16816(C2a, aL2h[kt], bl0, bl1);
            } else {
                mma16816(C2a, aL2h[kt], bh0, bh1);
                mma16816(C2b, aL2l[kt], bh0, bh1);
                mma16816(C2a, aL2h[kt], bl0, bl1);
            }
        }

        // Scatter gates: rows r0,r1 (L1), 256+r0,256+r1 (L2); cols 2lr, 2lr+1
        {
            const int cc = 2 * lr;
            *(float2*)&gbuf[r0 * 10 + cc]         = make_float2(C1a[0] + C1b[0], C1a[1] + C1b[1]);
            *(float2*)&gbuf[r1 * 10 + cc]         = make_float2(C1a[2] + C1b[2], C1a[3] + C1b[3]);
            *(float2*)&gbuf[(256 + r0) * 10 + cc] = make_float2(C2a[0] + C2b[0], C2a[1] + C2b[1]);
            *(float2*)&gbuf[(256 + r1) * 10 + cc] = make_float2(C2a[2] + C2b[2], C2a[3] + C2b[3]);
        }
        __syncthreads();

        const float xq = xcur;
        if (!grp && t + 1 < TLEN) xcur = xrow[t + 1];

        // ---- Pointwise: grp0 -> layer1 step t; grp1 -> layer2 step t-1 ----
        if (grp ? (t > 0) : (t < TLEN)) {
            const int gr = grp * 256 + pu;
            float g0 = fmaf(wx[0], xq, gbuf[(gr      ) * 10 + pb] + bb[0]);
            float g1 = fmaf(wx[1], xq, gbuf[(gr +  64) * 10 + pb] + bb[1]);
            float g2 = fmaf(wx[2], xq, gbuf[(gr + 128) * 10 + pb] + bb[2]);
            float g3 = fmaf(wx[3], xq, gbuf[(gr + 192) * 10 + pb] + bb[3]);
            const float iv = sigm_ap(g0);
            const float fv = sigm_ap(g1);
            const float gv = tanh_ap(g2);
            const float ov = sigm_ap(g3);
            cst = fmaf(fv, cst, iv * gv);
            const float h = ov * tanh_ap(cst);

            const int wbase = (t & 1) ? HB0 : HB1;
            uint16_t* whi = (uint16_t*)(smu + wbase);
            uint16_t* wlo = (uint16_t*)(smu + wbase + 544);
            const int hidx = pb * 136 + grp * 64 + pu;   // row stride 136 halves
            const __half hh = __float2half_rn(h);
            whi[hidx] = *(const uint16_t*)&hh;
            const __half hl = __float2half_rn(h - __half2float(hh));
            wlo[hidx] = *(const uint16_t*)&hl;
            if (grp) h2f[pb * HD + pu] = h;
        }
        __syncthreads();
    }

    // ================= Head =================
    {   // fc1: one (batch, out) per thread — 4*128 = 512
        int b = tid >> 7;
        int n = tid & 127;
        float acc = fc1_b[n];
        const float* wr = &fc1_w[n * HD];
        const float* hr = &h2f[b * HD];
        #pragma unroll
        for (int d = 0; d < HD; ++d) acc = fmaf(wr[d], hr[d], acc);
        ms[tid] = fmaxf(acc, 0.0f);
    }
    __syncthreads();
    if (tid < BPB * 10) {
        int b = tid / 10;
        int n = tid - b * 10;
        float acc = fc2_b[n];
        const float* wr = &fc2_w[n * 128];
        const float* mr = &ms[b * 128];
        #pragma unroll
        for (int k = 0; k < 128; ++k) acc = fmaf(wr[k], mr[k], acc);
        out[(bbase + b) * 10 + n] = acc;
    }
}

extern "C" void kernel_launch(void* const* d_in, const int* in_sizes, int n_in,
                              void* d_out, int out_size)
{
    const float* x     = (const float*)d_in[0];
    const float* w_ih0 = (const float*)d_in[1];
    const float* w_hh0 = (const float*)d_in[2];
    const float* b_ih0 = (const float*)d_in[3];
    const float* b_hh0 = (const float*)d_in[4];
    const float* w_ih1 = (const float*)d_in[5];
    const float* w_hh1 = (const float*)d_in[6];
    const float* b_ih1 = (const float*)d_in[7];
    const float* b_hh1 = (const float*)d_in[8];
    const float* fc1_w = (const float*)d_in[9];
    const float* fc1_b = (const float*)d_in[10];
    const float* fc2_w = (const float*)d_in[11];
    const float* fc2_b = (const float*)d_in[12];
    float* out = (float*)d_out;

    lstm2_mma_kernel<<<NBLOCKS, NTHREADS>>>(
        x, w_ih0, w_hh0, b_ih0, b_hh0,
        w_ih1, w_hh1, b_ih1, b_hh1,
        fc1_w, fc1_b, fc2_w, fc2_b, out);
}

// round 11
// speedup vs baseline: 1.2269x; 1.2269x over previous
#include <cuda_runtime.h>
#include <cuda_fp16.h>
#include <cstdint>

// Fixed shapes
#define TLEN 2048
#define HD   64
#define BPB  4
#define NTHREADS 512
#define NBLOCKS  128

// SMEM u32 layout: ping-pong fp16 B buffers (hi[8x68] + lo[8x68] each), h2 fp32, head scratch
#define HB0  0
#define HB1  1088
#define H2F  2176         // f32 [4*64]
#define MS   2432         // f32 [512]
#define SMEM_U32 2944

__device__ __forceinline__ float tanh_ap(float v) {
    float r;
    asm("tanh.approx.f32 %0, %1;" : "=f"(r) : "f"(v));
    return r;
}
__device__ __forceinline__ float sigm_ap(float v) {
    return fmaf(0.5f, tanh_ap(0.5f * v), 0.5f);
}
__device__ __forceinline__ uint32_t packh(float x, float y) {
    __half2 h = __floats2half2_rn(x, y);
    return *reinterpret_cast<uint32_t*>(&h);
}
__device__ __forceinline__ float lof(float x) {
    return x - __half2float(__float2half_rn(x));
}
__device__ __forceinline__ void mma16816(float* c, const uint32_t* a,
                                         uint32_t b0, uint32_t b1) {
    asm volatile(
        "mma.sync.aligned.m16n8k16.row.col.f32.f16.f16.f32 "
        "{%0,%1,%2,%3}, {%4,%5,%6,%7}, {%8,%9}, {%0,%1,%2,%3};"
        : "+f"(c[0]), "+f"(c[1]), "+f"(c[2]), "+f"(c[3])
        : "r"(a[0]), "r"(a[1]), "r"(a[2]), "r"(a[3]), "r"(b0), "r"(b1));
}

__global__ __launch_bounds__(NTHREADS, 1)
void lstm2_mma2_kernel(
    const float* __restrict__ x,      // [B, T]
    const float* __restrict__ w_ih0,  // [256, 1]
    const float* __restrict__ w_hh0,  // [256, 64]
    const float* __restrict__ b_ih0,  // [256]
    const float* __restrict__ b_hh0,  // [256]
    const float* __restrict__ w_ih1,  // [256, 64]
    const float* __restrict__ w_hh1,  // [256, 64]
    const float* __restrict__ b_ih1,  // [256]
    const float* __restrict__ b_hh1,  // [256]
    const float* __restrict__ fc1_w,  // [128, 64]
    const float* __restrict__ fc1_b,  // [128]
    const float* __restrict__ fc2_w,  // [10, 128]
    const float* __restrict__ fc2_b,  // [10]
    float* __restrict__ out)          // [B, 10]
{
    __shared__ uint32_t smu[SMEM_U32];
    float* h2f = (float*)(smu + H2F);
    float* ms  = (float*)(smu + MS);

    const int tid  = threadIdx.x;
    const int l    = tid & 31;
    const int w    = tid >> 5;        // warp 0..15 -> units 4w..4w+3
    const int lq   = l >> 2;          // tile row group 0..7
    const int lr   = l & 3;
    const int glo  = lq >> 2;         // 0: gates {i,g}; 1: gates {f,o}
    const int uu   = lq & 3;
    const int uglob = 4 * w + uu;     // hidden unit
    const int bk   = 2 * lr + glo;    // batch this thread finalizes (0..7; >=4 are pad)
    const int bbase = blockIdx.x * BPB;

    // Permuted gate rows for this thread's tile rows lq (R0) and lq+8 (R1):
    const int R0 = glo * 64 + uglob;          // gate glo
    const int R1 = (glo + 2) * 64 + uglob;    // gate glo+2

    // ---- Pack weights into register-resident A fragments (hi + lo fp16) ----
    uint32_t aL1h[4][4], aL1l[4][4], aL2h[8][4], aL2l[8][4];
    #pragma unroll
    for (int kt = 0; kt < 4; ++kt) {
        const int k = 16 * kt + 2 * lr;
        const float w00 = w_hh0[R0 * HD + k],     w01 = w_hh0[R0 * HD + k + 1];
        const float w10 = w_hh0[R1 * HD + k],     w11 = w_hh0[R1 * HD + k + 1];
        const float w02 = w_hh0[R0 * HD + k + 8], w03 = w_hh0[R0 * HD + k + 9];
        const float w12 = w_hh0[R1 * HD + k + 8], w13 = w_hh0[R1 * HD + k + 9];
        aL1h[kt][0] = packh(w00, w01); aL1h[kt][1] = packh(w10, w11);
        aL1h[kt][2] = packh(w02, w03); aL1h[kt][3] = packh(w12, w13);
        aL1l[kt][0] = packh(lof(w00), lof(w01)); aL1l[kt][1] = packh(lof(w10), lof(w11));
        aL1l[kt][2] = packh(lof(w02), lof(w03)); aL1l[kt][3] = packh(lof(w12), lof(w13));
    }
    #pragma unroll
    for (int kt = 0; kt < 8; ++kt) {
        const int k = 16 * kt + 2 * lr;
        const float* s0 = (k < 64) ? (w_ih1 + R0 * HD + k) : (w_hh1 + R0 * HD + k - 64);
        const float* s1 = (k < 64) ? (w_ih1 + R1 * HD + k) : (w_hh1 + R1 * HD + k - 64);
        const float w00 = s0[0], w01 = s0[1], w02 = s0[8], w03 = s0[9];
        const float w10 = s1[0], w11 = s1[1], w12 = s1[8], w13 = s1[9];
        aL2h[kt][0] = packh(w00, w01); aL2h[kt][1] = packh(w10, w11);
        aL2h[kt][2] = packh(w02, w03); aL2h[kt][3] = packh(w12, w13);
        aL2l[kt][0] = packh(lof(w00), lof(w01)); aL2l[kt][1] = packh(lof(w10), lof(w11));
        aL2l[kt][2] = packh(lof(w02), lof(w03)); aL2l[kt][3] = packh(lof(w12), lof(w13));
    }

    const float bA0  = b_ih0[R0] + b_hh0[R0];
    const float bA1  = b_ih0[R1] + b_hh0[R1];
    const float bE0  = b_ih1[R0] + b_hh1[R0];
    const float bE1  = b_ih1[R1] + b_hh1[R1];
    const float wxR0 = w_ih0[R0];
    const float wxR1 = w_ih0[R1];

    for (int i = tid; i < SMEM_U32; i += NTHREADS) smu[i] = 0u;
    __syncthreads();

    float cst1 = 0.0f, cst2 = 0.0f;
    const bool bval = (bk < BPB);
    const float* xrow = x + (bbase + (bval ? bk : 0)) * TLEN;
    float xcur = bval ? xrow[0] : 0.0f;

    // Pipelined: iter t computes L1 gates(t) and L2 gates(t-1); 1 barrier/step.
    for (int t = 0; t <= TLEN; ++t) {
        const uint32_t* rd_hi = smu + ((t & 1) ? HB1 : HB0);
        const uint32_t* rd_lo = rd_hi + 544;
        const int bidx = lq * 68 + lr;

        // x for B cols 2lr (xe) and 2lr+1 (xo2) via pair exchange
        const float xo  = __shfl_xor_sync(0xffffffffu, xcur, 16);
        const float xe  = glo ? xo : xcur;
        const float xo2 = glo ? xcur : xo;

        // Accumulators pre-loaded with bias (+ w_ih0*x for L1)
        float C1e[4] = { fmaf(wxR0, xe, bA0), fmaf(wxR0, xo2, bA0),
                         fmaf(wxR1, xe, bA1), fmaf(wxR1, xo2, bA1) };
        float C1o[4] = {0, 0, 0, 0};
        float C2e[4] = {bE0, bE0, bE1, bE1};
        float C2o[4] = {0, 0, 0, 0};

        #pragma unroll
        for (int kt = 0; kt < 8; ++kt) {
            const uint32_t bh0 = rd_hi[bidx + kt * 8];
            const uint32_t bh1 = rd_hi[bidx + kt * 8 + 4];
            const uint32_t bl0 = rd_lo[bidx + kt * 8];
            const uint32_t bl1 = rd_lo[bidx + kt * 8 + 4];
            float* C2 = (kt & 1) ? C2o : C2e;
            if (kt < 4) {
                float* C1 = (kt & 1) ? C1o : C1e;
                mma16816(C1, aL1h[kt], bh0, bh1);   // Whi*Bhi
                mma16816(C1, aL1l[kt], bh0, bh1);   // Wlo*Bhi
                mma16816(C1, aL1h[kt], bl0, bl1);   // Whi*Blo
            }
            mma16816(C2, aL2h[kt], bh0, bh1);
            mma16816(C2, aL2l[kt], bh0, bh1);
            mma16816(C2, aL2h[kt], bl0, bl1);
        }

        float c1v[4], c2v[4];
        #pragma unroll
        for (int i = 0; i < 4; ++i) { c1v[i] = C1e[i] + C1o[i]; c2v[i] = C2e[i] + C2o[i]; }

        // Gate-quad assembly via pair exchange (l <-> l^16), per layer.
        // glo=0 thread keeps batch 2lr (its gates i,g), glo=1 keeps 2lr+1 (f,o).
        const float k10 = glo ? c1v[1] : c1v[0];
        const float s10 = glo ? c1v[0] : c1v[1];
        const float k12 = glo ? c1v[3] : c1v[2];
        const float s12 = glo ? c1v[2] : c1v[3];
        const float r10 = __shfl_xor_sync(0xffffffffu, s10, 16);
        const float r12 = __shfl_xor_sync(0xffffffffu, s12, 16);
        const float g1i = glo ? r10 : k10;
        const float g1f = glo ? k10 : r10;
        const float g1g = glo ? r12 : k12;
        const float g1o = glo ? k12 : r12;

        const float k20 = glo ? c2v[1] : c2v[0];
        const float s20 = glo ? c2v[0] : c2v[1];
        const float k22 = glo ? c2v[3] : c2v[2];
        const float s22 = glo ? c2v[2] : c2v[3];
        const float r20 = __shfl_xor_sync(0xffffffffu, s20, 16);
        const float r22 = __shfl_xor_sync(0xffffffffu, s22, 16);
        const float g2i = glo ? r20 : k20;
        const float g2f = glo ? k20 : r20;
        const float g2g = glo ? r22 : k22;
        const float g2o = glo ? k22 : r22;

        const int wbase = (t & 1) ? HB0 : HB1;
        uint16_t* whi = (uint16_t*)(smu + wbase);
        uint16_t* wlo = (uint16_t*)(smu + wbase + 544);

        // L1 pointwise (step t): h1 -> halves [0,64) of write buffer
        if (t < TLEN) {
            const float iv = sigm_ap(g1i);
            const float fv = sigm_ap(g1f);
            const float gv = tanh_ap(g1g);
            const float ov = sigm_ap(g1o);
            cst1 = fmaf(fv, cst1, iv * gv);
            const float h = ov * tanh_ap(cst1);
            const __half hh = __float2half_rn(h);
            whi[bk * 136 + uglob] = *(const uint16_t*)&hh;
            const __half hl = __float2half_rn(h - __half2float(hh));
            wlo[bk * 136 + uglob] = *(const uint16_t*)&hl;
        }
        // L2 pointwise (step t-1): h2 -> halves [64,128)
        if (t > 0) {
            const float iv = sigm_ap(g2i);
            const float fv = sigm_ap(g2f);
            const float gv = tanh_ap(g2g);
            const float ov = sigm_ap(g2o);
            cst2 = fmaf(fv, cst2, iv * gv);
            const float h = ov * tanh_ap(cst2);
            const __half hh = __float2half_rn(h);
            whi[bk * 136 + 64 + uglob] = *(const uint16_t*)&hh;
            const __half hl = __float2half_rn(h - __half2float(hh));
            wlo[bk * 136 + 64 + uglob] = *(const uint16_t*)&hl;
            if (t == TLEN && bval) h2f[bk * HD + uglob] = h;
        }

        if (bval && t + 1 < TLEN) xcur = xrow[t + 1];
        __syncthreads();
    }

    // ================= Head =================
    {   // fc1: one (batch, out) per thread — 4*128 = 512
        int b = tid >> 7;
        int n = tid & 127;
        float acc = fc1_b[n];
        const float* wr = &fc1_w[n * HD];
        const float* hr = &h2f[b * HD];
        #pragma unroll
        for (int d = 0; d < HD; ++d) acc = fmaf(wr[d], hr[d], acc);
        ms[tid] = fmaxf(acc, 0.0f);
    }
    __syncthreads();
    if (tid < BPB * 10) {
        int b = tid / 10;
        int n = tid - b * 10;
        float acc = fc2_b[n];
        const float* wr = &fc2_w[n * 128];
        const float* mr = &ms[b * 128];
        #pragma unroll
        for (int k = 0; k < 128; ++k) acc = fmaf(wr[k], mr[k], acc);
        out[(bbase + b) * 10 + n] = acc;
    }
}

extern "C" void kernel_launch(void* const* d_in, const int* in_sizes, int n_in,
                              void* d_out, int out_size)
{
    const float* x     = (const float*)d_in[0];
    const float* w_ih0 = (const float*)d_in[1];
    const float* w_hh0 = (const float*)d_in[2];
    const float* b_ih0 = (const float*)d_in[3];
    const float* b_hh0 = (const float*)d_in[4];
    const float* w_ih1 = (const float*)d_in[5];
    const float* w_hh1 = (const float*)d_in[6];
    const float* b_ih1 = (const float*)d_in[7];
    const float* b_hh1 = (const float*)d_in[8];
    const float* fc1_w = (const float*)d_in[9];
    const float* fc1_b = (const float*)d_in[10];
    const float* fc2_w = (const float*)d_in[11];
    const float* fc2_b = (const float*)d_in[12];
    float* out = (float*)d_out;

    lstm2_mma2_kernel<<<NBLOCKS, NTHREADS>>>(
        x, w_ih0, w_hh0, b_ih0, b_hh0,
        w_ih1, w_hh1, b_ih1, b_hh1,
        fc1_w, fc1_b, fc2_w, fc2_b, out);
}